// round 13
// baseline (speedup 1.0000x reference)
#include <cuda_runtime.h>
#include <cuda_bf16.h>

// LandmarksLoss: mean((pred - true)^2), true = windowed 128x128 bell table.
//
// R13: R10 fused kernel (best: 41.7us) with ONE change — bell access is
// vectorized. yoff = 4q + rem (CTA-uniform); the 4 bell columns for a float4
// come from two aligned float4 loads bf4[ix][w4+q], bf4[ix][w4+q+1] (8 L1
// wavefronts instead of 16 from stride-16B scalar loads), assembled with a
// uniform rem-shift (9 SELs). Out-of-range f4 -> zero4 auto-masks elements
// (iy in [0,128) <=> source f4 index in [0,32)).

#define H_DIM     224
#define W_DIM     224
#define HW        (H_DIM * W_DIM)      // 50176
#define ROWF4     (W_DIM / 4)          // 56
#define NF4       (HW / 4)             // 12544
#define THREADS   256
#define NWARP     (THREADS / 32)
#define MAX_BL    4096
#define DELTA     128
#define DELTAF4   (DELTA / 4)          // 32 float4 per bell row
#define HALF      64

__device__ float        g_partials[MAX_BL];
__device__ unsigned int g_count = 0;

__device__ __forceinline__ float blockReduce(float v, float* s)
{
    #pragma unroll
    for (int off = 16; off > 0; off >>= 1)
        v += __shfl_down_sync(0xFFFFFFFFu, v, off);
    const int lane = threadIdx.x & 31;
    const int wid  = threadIdx.x >> 5;
    if (lane == 0) s[wid] = v;
    __syncthreads();
    if (wid == 0) {
        v = (lane < NWARP) ? s[lane] : 0.0f;
        #pragma unroll
        for (int off = NWARP / 2; off > 0; off >>= 1)
            v += __shfl_down_sync(0xFFFFFFFFu, v, off);
    }
    return v;  // valid in thread 0
}

__global__ void __launch_bounds__(THREADS, 8)
landmarks_fused(const float* __restrict__ pred,
                const float* __restrict__ lm,
                const float* __restrict__ bell,
                float* __restrict__ out,
                int n_bl, float inv_n)
{
    const int bl = blockIdx.x;
    const float4* img = reinterpret_cast<const float4*>(pred + (size_t)bl * HW);
    const float4* bf4 = reinterpret_cast<const float4*>(bell);

    // landmarks: [...,0] = y_r, [...,1] = x_r  (round-half-to-even = jnp.round)
    const int yr = (int)rintf(__ldg(&lm[2 * bl + 0]));
    const int xr = (int)rintf(__ldg(&lm[2 * bl + 1]));
    const int xoff = HALF - xr;          // bell row = h + xoff
    const int yoff = HALF - yr;          // bell col = w + yoff
    const int q    = yoff >> 2;          // floor-div 4 (CTA-uniform)
    const int rem  = yoff & 3;           // CTA-uniform
    const bool sh2 = (rem & 2) != 0;
    const bool sh1 = (rem & 1) != 0;

    float acc = 0.0f;

    #pragma unroll 4
    for (int i = threadIdx.x; i < NF4; i += THREADS) {
        const float4 p = __ldg(&img[i]);

        const int h  = i / ROWF4;
        const int w4 = i - h * ROWF4;

        const int ix = h + xoff;
        const bool rowok = ((unsigned)ix < (unsigned)DELTA);
        const int jf = w4 + q;           // first source f4 index in bell row

        float4 a = make_float4(0.f, 0.f, 0.f, 0.f);
        float4 b = make_float4(0.f, 0.f, 0.f, 0.f);
        const int rowbase = ix << 5;     // ix * 32 f4
        if (rowok && (unsigned)jf < (unsigned)DELTAF4)
            a = __ldg(&bf4[rowbase + jf]);
        if (rowok && (unsigned)(jf + 1) < (unsigned)DELTAF4)
            b = __ldg(&bf4[rowbase + jf + 1]);

        // Shift the 8-float window {a,b} left by rem (uniform predicates).
        float e0 = a.x, e1 = a.y, e2 = a.z, e3 = a.w, e4 = b.x;
        if (sh2) { e0 = a.z; e1 = a.w; e2 = b.x; e3 = b.y; e4 = b.z; }
        if (sh1) {
            e0 = e1; e1 = e2; e2 = e3;
            e3 = e4;
        }

        const float d0 = p.x - e0;
        const float d1 = p.y - e1;
        const float d2 = p.z - e2;
        const float d3 = p.w - e3;
        acc = fmaf(d0, d0, acc);
        acc = fmaf(d1, d1, acc);
        acc = fmaf(d2, d2, acc);
        acc = fmaf(d3, d3, acc);
    }

    __shared__ float s[NWARP];
    const float bsum = blockReduce(acc, s);

    __shared__ bool amLast;
    if (threadIdx.x == 0) {
        g_partials[bl] = bsum;
        __threadfence();
        const unsigned prev = atomicAdd(&g_count, 1u);
        amLast = (prev == (unsigned)(gridDim.x - 1));
    }
    __syncthreads();

    if (amLast) {
        // Deterministic final reduction: fixed index order every run.
        float tot = 0.0f;
        for (int i = threadIdx.x; i < n_bl; i += THREADS)
            tot += __ldcg(&g_partials[i]);
        __syncthreads();   // reuse s[] safely
        const float t = blockReduce(tot, s);
        if (threadIdx.x == 0) {
            out[0] = t * inv_n;
            g_count = 0;   // reset for next graph replay
        }
    }
}

extern "C" void kernel_launch(void* const* d_in, const int* in_sizes, int n_in,
                              void* d_out, int out_size)
{
    const float* pred = (const float*)d_in[0];  // (B, L, 224, 224)
    const float* lm   = (const float*)d_in[1];  // (B, L, 2)
    const float* bell = (const float*)d_in[2];  // (128, 128)
    float* out = (float*)d_out;

    const int n_bl = in_sizes[1] / 2;           // B*L = 1088
    const float inv_n = 1.0f / ((float)n_bl * (float)HW);

    landmarks_fused<<<n_bl, THREADS>>>(pred, lm, bell, out, n_bl, inv_n);
}